// round 8
// baseline (speedup 1.0000x reference)
#include <cuda_runtime.h>

#define N_NODES 50000
#define N_EDGES 800000
#define F_IN    128
#define F_HID   64
#define SCAN_B  1024
#define SCAN_NB ((N_NODES + SCAN_B - 1) / SCAN_B)   // 49
#define EQ      (N_EDGES / 4)                        // 200000 exact

// ---------------- scratch (no allocations allowed) ----------------
__device__ int   g_deg_out_i[N_NODES];   // zeroed at load; re-zeroed by scanC each call
__device__ int   g_deg_in_i [N_NODES];
__device__ float g_norm_out[N_NODES];
__device__ float g_norm_in [N_NODES];
__device__ int   g_off    [N_NODES + 1];
__device__ int   g_cursor [N_NODES];
__device__ int   g_bsum   [64];
__device__ int   g_bpre   [64];
__device__ int   g_ticket;               // reset by scanA's last block
__device__ int   g_csr_src[N_EDGES];
__device__ __align__(16) float g_h[N_NODES * F_HID];   // gemm output
__device__ __align__(16) float g_t[N_NODES * F_HID];   // post-layer1 acts (pre-scaled)

// ---------------- degree: 4 edges/thread, int4 loads ----------------
__global__ void count_deg_kernel(const int* __restrict__ src, const int* __restrict__ dst) {
    int t = blockIdx.x * blockDim.x + threadIdx.x;
    if (t < EQ) {
        int4 s4 = ((const int4*)src)[t];
        int4 d4 = ((const int4*)dst)[t];
        atomicAdd(&g_deg_out_i[s4.x], 1);
        atomicAdd(&g_deg_out_i[s4.y], 1);
        atomicAdd(&g_deg_out_i[s4.z], 1);
        atomicAdd(&g_deg_out_i[s4.w], 1);
        atomicAdd(&g_deg_in_i[d4.x], 1);
        atomicAdd(&g_deg_in_i[d4.y], 1);
        atomicAdd(&g_deg_in_i[d4.z], 1);
        atomicAdd(&g_deg_in_i[d4.w], 1);
    }
}

// ---------------- scan phase A: per-block scan + last block scans block sums ----------------
__global__ void __launch_bounds__(SCAN_B) scanA_kernel() {
    __shared__ int warp_sums[32];
    __shared__ int is_last;
    int tid = threadIdx.x;
    int lane = tid & 31, wid = tid >> 5;
    int i = blockIdx.x * SCAN_B + tid;
    int v = (i < N_NODES) ? g_deg_in_i[i] : 0;
    int x = v;
#pragma unroll
    for (int o = 1; o < 32; o <<= 1) {
        int y = __shfl_up_sync(0xffffffffu, x, o);
        if (lane >= o) x += y;
    }
    if (lane == 31) warp_sums[wid] = x;
    __syncthreads();
    if (wid == 0) {
        int s = warp_sums[lane];
#pragma unroll
        for (int o = 1; o < 32; o <<= 1) {
            int y = __shfl_up_sync(0xffffffffu, s, o);
            if (lane >= o) s += y;
        }
        warp_sums[lane] = s;
    }
    __syncthreads();
    int excl = (wid ? warp_sums[wid - 1] : 0) + x - v;
    if (i < N_NODES) g_off[i] = excl;
    if (tid == SCAN_B - 1) {
        g_bsum[blockIdx.x] = excl + v;
        __threadfence();
    }
    __syncthreads();
    if (tid == 0)
        is_last = (atomicAdd(&g_ticket, 1) == (int)gridDim.x - 1);
    __syncthreads();
    if (is_last && wid == 0) {
        __threadfence();
        int acc = 0;
        for (int b = 0; b < SCAN_NB; b += 32) {
            int t = b + lane;
            int bv = (t < SCAN_NB) ? g_bsum[t] : 0;
            int bx = bv;
#pragma unroll
            for (int o = 1; o < 32; o <<= 1) {
                int y = __shfl_up_sync(0xffffffffu, bx, o);
                if (lane >= o) bx += y;
            }
            if (t < SCAN_NB) g_bpre[t] = acc + bx - bv;
            acc += __shfl_sync(0xffffffffu, bx, 31);
        }
        if (lane == 0) g_ticket = 0;   // reset for next call
    }
}

// ---------------- scan phase C: finalize offsets + cursors + norms; re-zero degrees ----------------
__global__ void __launch_bounds__(SCAN_B) scanC_kernel() {
    int i = blockIdx.x * SCAN_B + threadIdx.x;
    if (i < N_NODES) {
        int off = g_off[i] + g_bpre[blockIdx.x];
        g_off[i] = off;
        g_cursor[i] = off;
        g_norm_out[i] = rsqrtf(fmaxf((float)g_deg_out_i[i], 1.f));
        g_norm_in [i] = rsqrtf(fmaxf((float)g_deg_in_i [i], 1.f));
        g_deg_out_i[i] = 0;            // ready for next call
        g_deg_in_i [i] = 0;
    }
    if (i == 0) g_off[N_NODES] = N_EDGES;
}

// ---------------- CSR fill: 4 edges/thread, int4 loads ----------------
__global__ void fill_kernel(const int* __restrict__ src, const int* __restrict__ dst) {
    int t = blockIdx.x * blockDim.x + threadIdx.x;
    if (t < EQ) {
        int4 s4 = ((const int4*)src)[t];
        int4 d4 = ((const int4*)dst)[t];
        int p0 = atomicAdd(&g_cursor[d4.x], 1);
        int p1 = atomicAdd(&g_cursor[d4.y], 1);
        int p2 = atomicAdd(&g_cursor[d4.z], 1);
        int p3 = atomicAdd(&g_cursor[d4.w], 1);
        g_csr_src[p0] = s4.x;
        g_csr_src[p1] = s4.y;
        g_csr_src[p2] = s4.z;
        g_csr_src[p3] = s4.w;
    }
}

// ---------------- GEMM1: g_h = (x * norm_out) @ W1  (K=128, N=64) ----------------
__global__ void __launch_bounds__(256) gemm1_kernel(const float* __restrict__ x,
                                                    const float* __restrict__ W) {
    __shared__ float Ws[F_IN * F_HID];    // 32 KB
    __shared__ float xs[64 * 129];        // 33 KB, pad->conflict-free
    int tid = threadIdx.x;
    for (int i = tid; i < F_IN * F_HID / 4; i += 256)
        ((float4*)Ws)[i] = ((const float4*)W)[i];
    int row0 = blockIdx.x * 64;
    for (int i = tid; i < 64 * 32; i += 256) {
        int r = i >> 5, kq = i & 31;
        int row = row0 + r;
        float4 v = make_float4(0.f, 0.f, 0.f, 0.f);
        float s = 0.f;
        if (row < N_NODES) {
            v = ((const float4*)x)[row * 32 + kq];
            s = g_norm_out[row];
        }
        float* p = &xs[r * 129 + kq * 4];
        p[0] = v.x * s; p[1] = v.y * s; p[2] = v.z * s; p[3] = v.w * s;
    }
    __syncthreads();
    int rg = tid >> 4;       // 0..15, rows rg + 16j
    int fg = tid & 15;       // feature quad
    float4 acc[4];
#pragma unroll
    for (int j = 0; j < 4; j++) acc[j] = make_float4(0.f, 0.f, 0.f, 0.f);
    const float4* Ws4 = (const float4*)Ws;
#pragma unroll 4
    for (int k = 0; k < F_IN; k++) {
        float4 w = Ws4[k * 16 + fg];
#pragma unroll
        for (int j = 0; j < 4; j++) {
            float a = xs[(rg + 16 * j) * 129 + k];
            acc[j].x += a * w.x; acc[j].y += a * w.y;
            acc[j].z += a * w.z; acc[j].w += a * w.w;
        }
    }
#pragma unroll
    for (int j = 0; j < 4; j++) {
        int row = row0 + rg + 16 * j;
        if (row < N_NODES) ((float4*)g_h)[row * 16 + fg] = acc[j];
    }
}

// ---------------- GEMM2: g_h = g_t @ W2  (K=64, N=64) ----------------
__global__ void __launch_bounds__(256) gemm2_kernel(const float* __restrict__ W) {
    __shared__ float Ws[F_HID * F_HID];   // 16 KB
    __shared__ float xs[64 * 65];         // 16.6 KB
    int tid = threadIdx.x;
    for (int i = tid; i < F_HID * F_HID / 4; i += 256)
        ((float4*)Ws)[i] = ((const float4*)W)[i];
    int row0 = blockIdx.x * 64;
    for (int i = tid; i < 64 * 16; i += 256) {
        int r = i >> 4, kq = i & 15;
        int row = row0 + r;
        float4 v = make_float4(0.f, 0.f, 0.f, 0.f);
        if (row < N_NODES) v = ((const float4*)g_t)[row * 16 + kq];
        float* p = &xs[r * 65 + kq * 4];
        p[0] = v.x; p[1] = v.y; p[2] = v.z; p[3] = v.w;
    }
    __syncthreads();
    int rg = tid >> 4;
    int fg = tid & 15;
    float4 acc[4];
#pragma unroll
    for (int j = 0; j < 4; j++) acc[j] = make_float4(0.f, 0.f, 0.f, 0.f);
    const float4* Ws4 = (const float4*)Ws;
#pragma unroll 4
    for (int k = 0; k < F_HID; k++) {
        float4 w = Ws4[k * 16 + fg];
#pragma unroll
        for (int j = 0; j < 4; j++) {
            float a = xs[(rg + 16 * j) * 65 + k];
            acc[j].x += a * w.x; acc[j].y += a * w.y;
            acc[j].z += a * w.z; acc[j].w += a * w.w;
        }
    }
#pragma unroll
    for (int j = 0; j < 4; j++) {
        int row = row0 + rg + 16 * j;
        if (row < N_NODES) ((float4*)g_h)[row * 16 + fg] = acc[j];
    }
}

// ---------------- gather core: one warp/node, float2/lane, 4-edge unroll ----------------
__device__ __forceinline__ float2 gather_sum(int node, int lane) {
    int beg = g_off[node], end = g_off[node + 1];
    const float2* h2 = (const float2*)g_h;
    float ax = 0.f, ay = 0.f, bx = 0.f, by = 0.f;
    float cx = 0.f, cy = 0.f, dx = 0.f, dy = 0.f;
    int j = beg;
    for (; j + 3 < end; j += 4) {
        int s0 = __ldg(&g_csr_src[j]);
        int s1 = __ldg(&g_csr_src[j + 1]);
        int s2 = __ldg(&g_csr_src[j + 2]);
        int s3 = __ldg(&g_csr_src[j + 3]);
        float2 v0 = h2[s0 * 32 + lane];
        float2 v1 = h2[s1 * 32 + lane];
        float2 v2 = h2[s2 * 32 + lane];
        float2 v3 = h2[s3 * 32 + lane];
        ax += v0.x; ay += v0.y;
        bx += v1.x; by += v1.y;
        cx += v2.x; cy += v2.y;
        dx += v3.x; dy += v3.y;
    }
    for (; j < end; j++) {
        int s = __ldg(&g_csr_src[j]);
        float2 v = h2[s * 32 + lane];
        ax += v.x; ay += v.y;
    }
    return make_float2(ax + bx + cx + dx, ay + by + cy + dy);
}

// ---------------- gather layer 1: g_t = relu(sum*norm_in + b1) * norm_out ----------------
__global__ void __launch_bounds__(256) gather1_kernel(const float* __restrict__ b1) {
    int node = blockIdx.x * 8 + (threadIdx.x >> 5);
    int lane = threadIdx.x & 31;
    if (node >= N_NODES) return;
    float2 a = gather_sum(node, lane);
    float ni = g_norm_in[node], no = g_norm_out[node];
    float2 bb = ((const float2*)b1)[lane];
    float2 o;
    o.x = fmaxf(a.x * ni + bb.x, 0.f) * no;
    o.y = fmaxf(a.y * ni + bb.y, 0.f) * no;
    ((float2*)g_t)[node * 32 + lane] = o;
}

// ---------------- gather layer 2: out = sum*norm_in + b2 ----------------
__global__ void __launch_bounds__(256) gather2_kernel(const float* __restrict__ b2,
                                                      float* __restrict__ out) {
    int node = blockIdx.x * 8 + (threadIdx.x >> 5);
    int lane = threadIdx.x & 31;
    if (node >= N_NODES) return;
    float2 a = gather_sum(node, lane);
    float ni = g_norm_in[node];
    float2 bb = ((const float2*)b2)[lane];
    float2 o;
    o.x = a.x * ni + bb.x;
    o.y = a.y * ni + bb.y;
    ((float2*)out)[node * 32 + lane] = o;
}

extern "C" void kernel_launch(void* const* d_in, const int* in_sizes, int n_in,
                              void* d_out, int out_size) {
    const float* x   = (const float*)d_in[0];
    const int*   src = (const int*)  d_in[1];
    const int*   dst = (const int*)  d_in[2];
    const float* W1  = (const float*)d_in[3];
    const float* b1  = (const float*)d_in[4];
    const float* W2  = (const float*)d_in[5];
    const float* b2  = (const float*)d_in[6];
    float* out = (float*)d_out;

    const int T = 256;
    const int eqBlocks     = (EQ + T - 1) / T;        // 782
    const int gemmBlocks   = (N_NODES + 63) / 64;     // 782
    const int gatherBlocks = (N_NODES + 7) / 8;       // 6250

    // degrees, norms, CSR
    count_deg_kernel<<<eqBlocks, T>>>(src, dst);
    scanA_kernel<<<SCAN_NB, SCAN_B>>>();
    scanC_kernel<<<SCAN_NB, SCAN_B>>>();
    fill_kernel<<<eqBlocks, T>>>(src, dst);

    // layer 1
    gemm1_kernel<<<gemmBlocks, T>>>(x, W1);
    gather1_kernel<<<gatherBlocks, T>>>(b1);

    // layer 2
    gemm2_kernel<<<gemmBlocks, T>>>(W2);
    gather2_kernel<<<gatherBlocks, T>>>(b2, out);
}

// round 10
// speedup vs baseline: 1.0306x; 1.0306x over previous
#include <cuda_runtime.h>

#define N_NODES 50000
#define N_EDGES 800000
#define F_IN    128
#define F_HID   64
#define SCAN_B  1024
#define SCAN_NB ((N_NODES + SCAN_B - 1) / SCAN_B)   // 49

// ---------------- scratch (no allocations allowed) ----------------
__device__ int   g_deg_out_i[N_NODES];   // zeroed at load; re-zeroed by scanC each call
__device__ int   g_deg_in_i [N_NODES];
__device__ float g_norm_out[N_NODES];
__device__ float g_norm_in [N_NODES];
__device__ int   g_off    [N_NODES + 1];
__device__ int   g_bsum   [64];
__device__ int   g_bpre   [64];
__device__ int   g_ticket;               // reset by scanA's last block
__device__ int   g_rank   [N_EDGES];     // edge rank within its dst bucket
__device__ int   g_csr_src[N_EDGES];
__device__ __align__(16) float g_h[N_NODES * F_HID];   // gemm output
__device__ __align__(16) float g_t[N_NODES * F_HID];   // post-layer1 acts (pre-scaled)

// ---------------- degree count + per-edge rank capture ----------------
__global__ void count_deg_kernel(const int* __restrict__ src, const int* __restrict__ dst) {
    int e = blockIdx.x * blockDim.x + threadIdx.x;
    if (e < N_EDGES) {
        atomicAdd(&g_deg_out_i[src[e]], 1);
        g_rank[e] = atomicAdd(&g_deg_in_i[dst[e]], 1);
    }
}

// ---------------- scan phase A: per-block scan + last block scans block sums ----------------
__global__ void __launch_bounds__(SCAN_B) scanA_kernel() {
    __shared__ int warp_sums[32];
    __shared__ int is_last;
    int tid = threadIdx.x;
    int lane = tid & 31, wid = tid >> 5;
    int i = blockIdx.x * SCAN_B + tid;
    int v = (i < N_NODES) ? g_deg_in_i[i] : 0;
    int x = v;
#pragma unroll
    for (int o = 1; o < 32; o <<= 1) {
        int y = __shfl_up_sync(0xffffffffu, x, o);
        if (lane >= o) x += y;
    }
    if (lane == 31) warp_sums[wid] = x;
    __syncthreads();
    if (wid == 0) {
        int s = warp_sums[lane];
#pragma unroll
        for (int o = 1; o < 32; o <<= 1) {
            int y = __shfl_up_sync(0xffffffffu, s, o);
            if (lane >= o) s += y;
        }
        warp_sums[lane] = s;
    }
    __syncthreads();
    int excl = (wid ? warp_sums[wid - 1] : 0) + x - v;
    if (i < N_NODES) g_off[i] = excl;
    if (tid == SCAN_B - 1) {
        g_bsum[blockIdx.x] = excl + v;
        __threadfence();
    }
    __syncthreads();
    if (tid == 0)
        is_last = (atomicAdd(&g_ticket, 1) == (int)gridDim.x - 1);
    __syncthreads();
    if (is_last && wid == 0) {
        __threadfence();
        int acc = 0;
        for (int b = 0; b < SCAN_NB; b += 32) {
            int t = b + lane;
            int bv = (t < SCAN_NB) ? g_bsum[t] : 0;
            int bx = bv;
#pragma unroll
            for (int o = 1; o < 32; o <<= 1) {
                int y = __shfl_up_sync(0xffffffffu, bx, o);
                if (lane >= o) bx += y;
            }
            if (t < SCAN_NB) g_bpre[t] = acc + bx - bv;
            acc += __shfl_sync(0xffffffffu, bx, 31);
        }
        if (lane == 0) g_ticket = 0;   // reset for next call
    }
}

// ---------------- scan phase C: finalize offsets + norms; re-zero degrees ----------------
__global__ void __launch_bounds__(SCAN_B) scanC_kernel() {
    int i = blockIdx.x * SCAN_B + threadIdx.x;
    if (i < N_NODES) {
        int off = g_off[i] + g_bpre[blockIdx.x];
        g_off[i] = off;
        g_norm_out[i] = rsqrtf(fmaxf((float)g_deg_out_i[i], 1.f));
        g_norm_in [i] = rsqrtf(fmaxf((float)g_deg_in_i [i], 1.f));
        g_deg_out_i[i] = 0;            // ready for next call
        g_deg_in_i [i] = 0;
    }
    if (i == 0) g_off[N_NODES] = N_EDGES;
}

// ---------------- CSR fill: atomic-free (off[dst] + precomputed rank) ----------------
__global__ void fill_kernel(const int* __restrict__ src, const int* __restrict__ dst) {
    int e = blockIdx.x * blockDim.x + threadIdx.x;
    if (e < N_EDGES) {
        int pos = __ldg(&g_off[dst[e]]) + g_rank[e];
        g_csr_src[pos] = src[e];
    }
}

// ---------------- GEMM1: g_h = (x * norm_out) @ W1  (K=128, N=64) ----------------
__global__ void __launch_bounds__(256) gemm1_kernel(const float* __restrict__ x,
                                                    const float* __restrict__ W) {
    __shared__ float Ws[F_IN * F_HID];    // 32 KB
    __shared__ float xs[64 * 129];        // 33 KB, pad->conflict-free
    int tid = threadIdx.x;
    for (int i = tid; i < F_IN * F_HID / 4; i += 256)
        ((float4*)Ws)[i] = ((const float4*)W)[i];
    int row0 = blockIdx.x * 64;
    for (int i = tid; i < 64 * 32; i += 256) {
        int r = i >> 5, kq = i & 31;
        int row = row0 + r;
        float4 v = make_float4(0.f, 0.f, 0.f, 0.f);
        float s = 0.f;
        if (row < N_NODES) {
            v = ((const float4*)x)[row * 32 + kq];
            s = g_norm_out[row];
        }
        float* p = &xs[r * 129 + kq * 4];
        p[0] = v.x * s; p[1] = v.y * s; p[2] = v.z * s; p[3] = v.w * s;
    }
    __syncthreads();
    int rg = tid >> 4;       // 0..15, rows rg + 16j
    int fg = tid & 15;       // feature quad
    float4 acc[4];
#pragma unroll
    for (int j = 0; j < 4; j++) acc[j] = make_float4(0.f, 0.f, 0.f, 0.f);
    const float4* Ws4 = (const float4*)Ws;
#pragma unroll 4
    for (int k = 0; k < F_IN; k++) {
        float4 w = Ws4[k * 16 + fg];
#pragma unroll
        for (int j = 0; j < 4; j++) {
            float a = xs[(rg + 16 * j) * 129 + k];
            acc[j].x += a * w.x; acc[j].y += a * w.y;
            acc[j].z += a * w.z; acc[j].w += a * w.w;
        }
    }
#pragma unroll
    for (int j = 0; j < 4; j++) {
        int row = row0 + rg + 16 * j;
        if (row < N_NODES) ((float4*)g_h)[row * 16 + fg] = acc[j];
    }
}

// ---------------- GEMM2: g_h = g_t @ W2  (K=64, N=64) ----------------
__global__ void __launch_bounds__(256) gemm2_kernel(const float* __restrict__ W) {
    __shared__ float Ws[F_HID * F_HID];   // 16 KB
    __shared__ float xs[64 * 65];         // 16.6 KB
    int tid = threadIdx.x;
    for (int i = tid; i < F_HID * F_HID / 4; i += 256)
        ((float4*)Ws)[i] = ((const float4*)W)[i];
    int row0 = blockIdx.x * 64;
    for (int i = tid; i < 64 * 16; i += 256) {
        int r = i >> 4, kq = i & 15;
        int row = row0 + r;
        float4 v = make_float4(0.f, 0.f, 0.f, 0.f);
        if (row < N_NODES) v = ((const float4*)g_t)[row * 16 + kq];
        float* p = &xs[r * 65 + kq * 4];
        p[0] = v.x; p[1] = v.y; p[2] = v.z; p[3] = v.w;
    }
    __syncthreads();
    int rg = tid >> 4;
    int fg = tid & 15;
    float4 acc[4];
#pragma unroll
    for (int j = 0; j < 4; j++) acc[j] = make_float4(0.f, 0.f, 0.f, 0.f);
    const float4* Ws4 = (const float4*)Ws;
#pragma unroll 4
    for (int k = 0; k < F_HID; k++) {
        float4 w = Ws4[k * 16 + fg];
#pragma unroll
        for (int j = 0; j < 4; j++) {
            float a = xs[(rg + 16 * j) * 65 + k];
            acc[j].x += a * w.x; acc[j].y += a * w.y;
            acc[j].z += a * w.z; acc[j].w += a * w.w;
        }
    }
#pragma unroll
    for (int j = 0; j < 4; j++) {
        int row = row0 + rg + 16 * j;
        if (row < N_NODES) ((float4*)g_h)[row * 16 + fg] = acc[j];
    }
}

// ---------------- gather core: one warp/node, float2/lane, 4-edge unroll ----------------
__device__ __forceinline__ float2 gather_sum(int node, int lane) {
    int beg = g_off[node], end = g_off[node + 1];
    const float2* h2 = (const float2*)g_h;
    float ax = 0.f, ay = 0.f, bx = 0.f, by = 0.f;
    float cx = 0.f, cy = 0.f, dx = 0.f, dy = 0.f;
    int j = beg;
    for (; j + 3 < end; j += 4) {
        int s0 = __ldg(&g_csr_src[j]);
        int s1 = __ldg(&g_csr_src[j + 1]);
        int s2 = __ldg(&g_csr_src[j + 2]);
        int s3 = __ldg(&g_csr_src[j + 3]);
        float2 v0 = h2[s0 * 32 + lane];
        float2 v1 = h2[s1 * 32 + lane];
        float2 v2 = h2[s2 * 32 + lane];
        float2 v3 = h2[s3 * 32 + lane];
        ax += v0.x; ay += v0.y;
        bx += v1.x; by += v1.y;
        cx += v2.x; cy += v2.y;
        dx += v3.x; dy += v3.y;
    }
    for (; j < end; j++) {
        int s = __ldg(&g_csr_src[j]);
        float2 v = h2[s * 32 + lane];
        ax += v.x; ay += v.y;
    }
    return make_float2(ax + bx + cx + dx, ay + by + cy + dy);
}

// ---------------- gather layer 1: g_t = relu(sum*norm_in + b1) * norm_out ----------------
__global__ void __launch_bounds__(256) gather1_kernel(const float* __restrict__ b1) {
    int node = blockIdx.x * 8 + (threadIdx.x >> 5);
    int lane = threadIdx.x & 31;
    if (node >= N_NODES) return;
    float2 a = gather_sum(node, lane);
    float ni = g_norm_in[node], no = g_norm_out[node];
    float2 bb = ((const float2*)b1)[lane];
    float2 o;
    o.x = fmaxf(a.x * ni + bb.x, 0.f) * no;
    o.y = fmaxf(a.y * ni + bb.y, 0.f) * no;
    ((float2*)g_t)[node * 32 + lane] = o;
}

// ---------------- gather layer 2: out = sum*norm_in + b2 ----------------
__global__ void __launch_bounds__(256) gather2_kernel(const float* __restrict__ b2,
                                                      float* __restrict__ out) {
    int node = blockIdx.x * 8 + (threadIdx.x >> 5);
    int lane = threadIdx.x & 31;
    if (node >= N_NODES) return;
    float2 a = gather_sum(node, lane);
    float ni = g_norm_in[node];
    float2 bb = ((const float2*)b2)[lane];
    float2 o;
    o.x = a.x * ni + bb.x;
    o.y = a.y * ni + bb.y;
    ((float2*)out)[node * 32 + lane] = o;
}

extern "C" void kernel_launch(void* const* d_in, const int* in_sizes, int n_in,
                              void* d_out, int out_size) {
    const float* x   = (const float*)d_in[0];
    const int*   src = (const int*)  d_in[1];
    const int*   dst = (const int*)  d_in[2];
    const float* W1  = (const float*)d_in[3];
    const float* b1  = (const float*)d_in[4];
    const float* W2  = (const float*)d_in[5];
    const float* b2  = (const float*)d_in[6];
    float* out = (float*)d_out;

    const int T = 256;
    const int edgeBlocks   = (N_EDGES + T - 1) / T;   // 3125
    const int gemmBlocks   = (N_NODES + 63) / 64;     // 782
    const int gatherBlocks = (N_NODES + 7) / 8;       // 6250

    // degrees, norms, CSR
    count_deg_kernel<<<edgeBlocks, T>>>(src, dst);
    scanA_kernel<<<SCAN_NB, SCAN_B>>>();
    scanC_kernel<<<SCAN_NB, SCAN_B>>>();
    fill_kernel<<<edgeBlocks, T>>>(src, dst);

    // layer 1
    gemm1_kernel<<<gemmBlocks, T>>>(x, W1);
    gather1_kernel<<<gatherBlocks, T>>>(b1);

    // layer 2
    gemm2_kernel<<<gemmBlocks, T>>>(W2);
    gather2_kernel<<<gatherBlocks, T>>>(b2, out);
}

// round 11
// speedup vs baseline: 1.0497x; 1.0186x over previous
#include <cuda_runtime.h>
#include <cuda_fp16.h>

#define N_NODES 50000
#define N_EDGES 800000
#define F_IN    128
#define F_HID   64
#define SCAN_B  1024
#define SCAN_NB ((N_NODES + SCAN_B - 1) / SCAN_B)   // 49
#define EQ      (N_EDGES / 4)                        // 200000 exact

// ---------------- scratch (no allocations allowed) ----------------
__device__ int   g_deg_out_i[N_NODES];   // zeroed at load; re-zeroed by scanC each call
__device__ int   g_deg_in_i [N_NODES];
__device__ float g_norm_out[N_NODES];
__device__ float g_norm_in [N_NODES];
__device__ int   g_off    [N_NODES + 1];
__device__ int   g_bsum   [64];
__device__ int   g_bpre   [64];
__device__ int   g_ticket;               // reset by scanA's last block
__device__ int   g_rank   [N_EDGES];     // edge rank within its dst bucket
__device__ int   g_csr_src[N_EDGES];
__device__ __align__(16) __half g_h[N_NODES * F_HID]; // gemm output, fp16 (128B rows)
__device__ __align__(16) float  g_t[N_NODES * F_HID]; // post-layer1 acts (pre-scaled, fp32)

// ---------------- degree count + per-edge rank capture ----------------
__global__ void count_deg_kernel(const int* __restrict__ src, const int* __restrict__ dst) {
    int e = blockIdx.x * blockDim.x + threadIdx.x;
    if (e < N_EDGES) {
        atomicAdd(&g_deg_out_i[src[e]], 1);
        g_rank[e] = atomicAdd(&g_deg_in_i[dst[e]], 1);
    }
}

// ---------------- scan phase A: per-block scan + last block scans block sums ----------------
__global__ void __launch_bounds__(SCAN_B) scanA_kernel() {
    __shared__ int warp_sums[32];
    __shared__ int is_last;
    int tid = threadIdx.x;
    int lane = tid & 31, wid = tid >> 5;
    int i = blockIdx.x * SCAN_B + tid;
    int v = (i < N_NODES) ? g_deg_in_i[i] : 0;
    int x = v;
#pragma unroll
    for (int o = 1; o < 32; o <<= 1) {
        int y = __shfl_up_sync(0xffffffffu, x, o);
        if (lane >= o) x += y;
    }
    if (lane == 31) warp_sums[wid] = x;
    __syncthreads();
    if (wid == 0) {
        int s = warp_sums[lane];
#pragma unroll
        for (int o = 1; o < 32; o <<= 1) {
            int y = __shfl_up_sync(0xffffffffu, s, o);
            if (lane >= o) s += y;
        }
        warp_sums[lane] = s;
    }
    __syncthreads();
    int excl = (wid ? warp_sums[wid - 1] : 0) + x - v;
    if (i < N_NODES) g_off[i] = excl;
    if (tid == SCAN_B - 1) {
        g_bsum[blockIdx.x] = excl + v;
        __threadfence();
    }
    __syncthreads();
    if (tid == 0)
        is_last = (atomicAdd(&g_ticket, 1) == (int)gridDim.x - 1);
    __syncthreads();
    if (is_last && wid == 0) {
        __threadfence();
        int acc = 0;
        for (int b = 0; b < SCAN_NB; b += 32) {
            int t = b + lane;
            int bv = (t < SCAN_NB) ? g_bsum[t] : 0;
            int bx = bv;
#pragma unroll
            for (int o = 1; o < 32; o <<= 1) {
                int y = __shfl_up_sync(0xffffffffu, bx, o);
                if (lane >= o) bx += y;
            }
            if (t < SCAN_NB) g_bpre[t] = acc + bx - bv;
            acc += __shfl_sync(0xffffffffu, bx, 31);
        }
        if (lane == 0) g_ticket = 0;   // reset for next call
    }
}

// ---------------- scan phase C: finalize offsets + norms; re-zero degrees ----------------
__global__ void __launch_bounds__(SCAN_B) scanC_kernel() {
    int i = blockIdx.x * SCAN_B + threadIdx.x;
    if (i < N_NODES) {
        int off = g_off[i] + g_bpre[blockIdx.x];
        g_off[i] = off;
        g_norm_out[i] = rsqrtf(fmaxf((float)g_deg_out_i[i], 1.f));
        g_norm_in [i] = rsqrtf(fmaxf((float)g_deg_in_i [i], 1.f));
        g_deg_out_i[i] = 0;            // ready for next call
        g_deg_in_i [i] = 0;
    }
    if (i == 0) g_off[N_NODES] = N_EDGES;
}

// ---------------- CSR fill: atomic-free, 4 edges/thread for MLP ----------------
__global__ void fill_kernel(const int* __restrict__ src, const int* __restrict__ dst) {
    int t = blockIdx.x * blockDim.x + threadIdx.x;
    if (t < EQ) {
        int4 s4 = ((const int4*)src)[t];
        int4 d4 = ((const int4*)dst)[t];
        int4 r4 = ((const int4*)g_rank)[t];
        int p0 = __ldg(&g_off[d4.x]) + r4.x;
        int p1 = __ldg(&g_off[d4.y]) + r4.y;
        int p2 = __ldg(&g_off[d4.z]) + r4.z;
        int p3 = __ldg(&g_off[d4.w]) + r4.w;
        g_csr_src[p0] = s4.x;
        g_csr_src[p1] = s4.y;
        g_csr_src[p2] = s4.z;
        g_csr_src[p3] = s4.w;
    }
}

// ---------------- fp16 pack helper ----------------
__device__ __forceinline__ void store_half4(__half* base, float4 a) {
    union { __half2 h[2]; uint2 u; } pk;
    pk.h[0] = __floats2half2_rn(a.x, a.y);
    pk.h[1] = __floats2half2_rn(a.z, a.w);
    *reinterpret_cast<uint2*>(base) = pk.u;
}

// ---------------- GEMM1: g_h = fp16((x * norm_out) @ W1)  (K=128, N=64) ----------------
__global__ void __launch_bounds__(256) gemm1_kernel(const float* __restrict__ x,
                                                    const float* __restrict__ W) {
    __shared__ float Ws[F_IN * F_HID];    // 32 KB
    __shared__ float xs[64 * 129];        // 33 KB, pad->conflict-free
    int tid = threadIdx.x;
    for (int i = tid; i < F_IN * F_HID / 4; i += 256)
        ((float4*)Ws)[i] = ((const float4*)W)[i];
    int row0 = blockIdx.x * 64;
    for (int i = tid; i < 64 * 32; i += 256) {
        int r = i >> 5, kq = i & 31;
        int row = row0 + r;
        float4 v = make_float4(0.f, 0.f, 0.f, 0.f);
        float s = 0.f;
        if (row < N_NODES) {
            v = ((const float4*)x)[row * 32 + kq];
            s = g_norm_out[row];
        }
        float* p = &xs[r * 129 + kq * 4];
        p[0] = v.x * s; p[1] = v.y * s; p[2] = v.z * s; p[3] = v.w * s;
    }
    __syncthreads();
    int rg = tid >> 4;       // 0..15, rows rg + 16j
    int fg = tid & 15;       // feature quad
    float4 acc[4];
#pragma unroll
    for (int j = 0; j < 4; j++) acc[j] = make_float4(0.f, 0.f, 0.f, 0.f);
    const float4* Ws4 = (const float4*)Ws;
#pragma unroll 4
    for (int k = 0; k < F_IN; k++) {
        float4 w = Ws4[k * 16 + fg];
#pragma unroll
        for (int j = 0; j < 4; j++) {
            float a = xs[(rg + 16 * j) * 129 + k];
            acc[j].x += a * w.x; acc[j].y += a * w.y;
            acc[j].z += a * w.z; acc[j].w += a * w.w;
        }
    }
#pragma unroll
    for (int j = 0; j < 4; j++) {
        int row = row0 + rg + 16 * j;
        if (row < N_NODES) store_half4(&g_h[row * F_HID + fg * 4], acc[j]);
    }
}

// ---------------- GEMM2: g_h = fp16(g_t @ W2)  (K=64, N=64) ----------------
__global__ void __launch_bounds__(256) gemm2_kernel(const float* __restrict__ W) {
    __shared__ float Ws[F_HID * F_HID];   // 16 KB
    __shared__ float xs[64 * 65];         // 16.6 KB
    int tid = threadIdx.x;
    for (int i = tid; i < F_HID * F_HID / 4; i += 256)
        ((float4*)Ws)[i] = ((const float4*)W)[i];
    int row0 = blockIdx.x * 64;
    for (int i = tid; i < 64 * 16; i += 256) {
        int r = i >> 4, kq = i & 15;
        int row = row0 + r;
        float4 v = make_float4(0.f, 0.f, 0.f, 0.f);
        if (row < N_NODES) v = ((const float4*)g_t)[row * 16 + kq];
        float* p = &xs[r * 65 + kq * 4];
        p[0] = v.x; p[1] = v.y; p[2] = v.z; p[3] = v.w;
    }
    __syncthreads();
    int rg = tid >> 4;
    int fg = tid & 15;
    float4 acc[4];
#pragma unroll
    for (int j = 0; j < 4; j++) acc[j] = make_float4(0.f, 0.f, 0.f, 0.f);
    const float4* Ws4 = (const float4*)Ws;
#pragma unroll 4
    for (int k = 0; k < F_HID; k++) {
        float4 w = Ws4[k * 16 + fg];
#pragma unroll
        for (int j = 0; j < 4; j++) {
            float a = xs[(rg + 16 * j) * 65 + k];
            acc[j].x += a * w.x; acc[j].y += a * w.y;
            acc[j].z += a * w.z; acc[j].w += a * w.w;
        }
    }
#pragma unroll
    for (int j = 0; j < 4; j++) {
        int row = row0 + rg + 16 * j;
        if (row < N_NODES) store_half4(&g_h[row * F_HID + fg * 4], acc[j]);
    }
}

// ---------------- gather core: one warp/node, half2/lane (128B rows), 4-edge unroll ----------------
__device__ __forceinline__ float2 gather_sum(int node, int lane) {
    int beg = g_off[node], end = g_off[node + 1];
    const __half2* h2 = (const __half2*)g_h;
    float ax = 0.f, ay = 0.f, bx = 0.f, by = 0.f;
    float cx = 0.f, cy = 0.f, dx = 0.f, dy = 0.f;
    int j = beg;
    for (; j + 3 < end; j += 4) {
        int s0 = __ldg(&g_csr_src[j]);
        int s1 = __ldg(&g_csr_src[j + 1]);
        int s2 = __ldg(&g_csr_src[j + 2]);
        int s3 = __ldg(&g_csr_src[j + 3]);
        float2 v0 = __half22float2(h2[s0 * 32 + lane]);
        float2 v1 = __half22float2(h2[s1 * 32 + lane]);
        float2 v2 = __half22float2(h2[s2 * 32 + lane]);
        float2 v3 = __half22float2(h2[s3 * 32 + lane]);
        ax += v0.x; ay += v0.y;
        bx += v1.x; by += v1.y;
        cx += v2.x; cy += v2.y;
        dx += v3.x; dy += v3.y;
    }
    for (; j < end; j++) {
        int s = __ldg(&g_csr_src[j]);
        float2 v = __half22float2(h2[s * 32 + lane]);
        ax += v.x; ay += v.y;
    }
    return make_float2(ax + bx + cx + dx, ay + by + cy + dy);
}

// ---------------- gather layer 1: g_t = relu(sum*norm_in + b1) * norm_out ----------------
__global__ void __launch_bounds__(256) gather1_kernel(const float* __restrict__ b1) {
    int node = blockIdx.x * 8 + (threadIdx.x >> 5);
    int lane = threadIdx.x & 31;
    if (node >= N_NODES) return;
    float2 a = gather_sum(node, lane);
    float ni = g_norm_in[node], no = g_norm_out[node];
    float2 bb = ((const float2*)b1)[lane];
    float2 o;
    o.x = fmaxf(a.x * ni + bb.x, 0.f) * no;
    o.y = fmaxf(a.y * ni + bb.y, 0.f) * no;
    ((float2*)g_t)[node * 32 + lane] = o;
}

// ---------------- gather layer 2: out = sum*norm_in + b2 ----------------
__global__ void __launch_bounds__(256) gather2_kernel(const float* __restrict__ b2,
                                                      float* __restrict__ out) {
    int node = blockIdx.x * 8 + (threadIdx.x >> 5);
    int lane = threadIdx.x & 31;
    if (node >= N_NODES) return;
    float2 a = gather_sum(node, lane);
    float ni = g_norm_in[node];
    float2 bb = ((const float2*)b2)[lane];
    float2 o;
    o.x = a.x * ni + bb.x;
    o.y = a.y * ni + bb.y;
    ((float2*)out)[node * 32 + lane] = o;
}

extern "C" void kernel_launch(void* const* d_in, const int* in_sizes, int n_in,
                              void* d_out, int out_size) {
    const float* x   = (const float*)d_in[0];
    const int*   src = (const int*)  d_in[1];
    const int*   dst = (const int*)  d_in[2];
    const float* W1  = (const float*)d_in[3];
    const float* b1  = (const float*)d_in[4];
    const float* W2  = (const float*)d_in[5];
    const float* b2  = (const float*)d_in[6];
    float* out = (float*)d_out;

    const int T = 256;
    const int edgeBlocks   = (N_EDGES + T - 1) / T;   // 3125
    const int eqBlocks     = (EQ + T - 1) / T;        // 782
    const int gemmBlocks   = (N_NODES + 63) / 64;     // 782
    const int gatherBlocks = (N_NODES + 7) / 8;       // 6250

    // degrees, norms, CSR
    count_deg_kernel<<<edgeBlocks, T>>>(src, dst);
    scanA_kernel<<<SCAN_NB, SCAN_B>>>();
    scanC_kernel<<<SCAN_NB, SCAN_B>>>();
    fill_kernel<<<eqBlocks, T>>>(src, dst);

    // layer 1
    gemm1_kernel<<<gemmBlocks, T>>>(x, W1);
    gather1_kernel<<<gatherBlocks, T>>>(b1);

    // layer 2
    gemm2_kernel<<<gemmBlocks, T>>>(W2);
    gather2_kernel<<<gatherBlocks, T>>>(b2, out);
}

// round 12
// speedup vs baseline: 1.3876x; 1.3219x over previous
#include <cuda_runtime.h>
#include <cuda_fp16.h>
#include <mma.h>

using namespace nvcuda;

#define N_NODES 50000
#define N_EDGES 800000
#define F_IN    128
#define F_HID   64
#define SCAN_B  1024
#define SCAN_NB ((N_NODES + SCAN_B - 1) / SCAN_B)   // 49

// ---------------- scratch (no allocations allowed) ----------------
__device__ int   g_deg_out_i[N_NODES];   // zeroed at load; re-zeroed by scanC each call
__device__ int   g_deg_in_i [N_NODES];
__device__ float g_norm_out[N_NODES];
__device__ float g_norm_in [N_NODES];
__device__ int   g_off    [N_NODES + 1];
__device__ int   g_bsum   [64];
__device__ int   g_bpre   [64];
__device__ int   g_ticket;               // reset by scanA's last block
__device__ int   g_rank   [N_EDGES];     // edge rank within its dst bucket
__device__ int   g_csr_src[N_EDGES];
__device__ __align__(16) __half g_h[N_NODES * F_HID]; // gemm output, fp16 (128B rows)
__device__ __align__(16) __half g_t[N_NODES * F_HID]; // post-layer1 acts (pre-scaled, fp16)

// ---------------- degree count + per-edge rank capture ----------------
__global__ void count_deg_kernel(const int* __restrict__ src, const int* __restrict__ dst) {
    int e = blockIdx.x * blockDim.x + threadIdx.x;
    if (e < N_EDGES) {
        atomicAdd(&g_deg_out_i[src[e]], 1);
        g_rank[e] = atomicAdd(&g_deg_in_i[dst[e]], 1);
    }
}

// ---------------- scan phase A ----------------
__global__ void __launch_bounds__(SCAN_B) scanA_kernel() {
    __shared__ int warp_sums[32];
    __shared__ int is_last;
    int tid = threadIdx.x;
    int lane = tid & 31, wid = tid >> 5;
    int i = blockIdx.x * SCAN_B + tid;
    int v = (i < N_NODES) ? g_deg_in_i[i] : 0;
    int x = v;
#pragma unroll
    for (int o = 1; o < 32; o <<= 1) {
        int y = __shfl_up_sync(0xffffffffu, x, o);
        if (lane >= o) x += y;
    }
    if (lane == 31) warp_sums[wid] = x;
    __syncthreads();
    if (wid == 0) {
        int s = warp_sums[lane];
#pragma unroll
        for (int o = 1; o < 32; o <<= 1) {
            int y = __shfl_up_sync(0xffffffffu, s, o);
            if (lane >= o) s += y;
        }
        warp_sums[lane] = s;
    }
    __syncthreads();
    int excl = (wid ? warp_sums[wid - 1] : 0) + x - v;
    if (i < N_NODES) g_off[i] = excl;
    if (tid == SCAN_B - 1) {
        g_bsum[blockIdx.x] = excl + v;
        __threadfence();
    }
    __syncthreads();
    if (tid == 0)
        is_last = (atomicAdd(&g_ticket, 1) == (int)gridDim.x - 1);
    __syncthreads();
    if (is_last && wid == 0) {
        __threadfence();
        int acc = 0;
        for (int b = 0; b < SCAN_NB; b += 32) {
            int t = b + lane;
            int bv = (t < SCAN_NB) ? g_bsum[t] : 0;
            int bx = bv;
#pragma unroll
            for (int o = 1; o < 32; o <<= 1) {
                int y = __shfl_up_sync(0xffffffffu, bx, o);
                if (lane >= o) bx += y;
            }
            if (t < SCAN_NB) g_bpre[t] = acc + bx - bv;
            acc += __shfl_sync(0xffffffffu, bx, 31);
        }
        if (lane == 0) g_ticket = 0;
    }
}

// ---------------- scan phase C: finalize offsets + norms; re-zero degrees ----------------
__global__ void __launch_bounds__(SCAN_B) scanC_kernel() {
    int i = blockIdx.x * SCAN_B + threadIdx.x;
    if (i < N_NODES) {
        int off = g_off[i] + g_bpre[blockIdx.x];
        g_off[i] = off;
        g_norm_out[i] = rsqrtf(fmaxf((float)g_deg_out_i[i], 1.f));
        g_norm_in [i] = rsqrtf(fmaxf((float)g_deg_in_i [i], 1.f));
        g_deg_out_i[i] = 0;
        g_deg_in_i [i] = 0;
    }
    if (i == 0) g_off[N_NODES] = N_EDGES;
}

// ---------------- CSR fill: atomic-free scalar (measured best) ----------------
__global__ void fill_kernel(const int* __restrict__ src, const int* __restrict__ dst) {
    int e = blockIdx.x * blockDim.x + threadIdx.x;
    if (e < N_EDGES) {
        int pos = __ldg(&g_off[dst[e]]) + g_rank[e];
        g_csr_src[pos] = src[e];
    }
}

// ---------------- GEMM1 (wmma fp16): g_h = fp16((x * norm_out) @ W1) ----------------
// 128 threads = 4 warps; block = 64 rows; warp = 16 rows x 64 cols; K=128 in 8 steps.
__global__ void __launch_bounds__(128) gemm1_kernel(const float* __restrict__ x,
                                                    const float* __restrict__ W) {
    __shared__ __align__(16) char blob[64 * 136 * 2 + 128 * 72 * 2];  // 35840 B
    __half* xh = (__half*)blob;                    // [64][136]
    __half* wh = (__half*)(blob + 64 * 136 * 2);   // [128][72]
    float*  cs = (float*)blob;                     // [64][64], reused after compute
    int tid = threadIdx.x;
    int wid = tid >> 5;
    int row0 = blockIdx.x * 64;

    // load W1 (128x64 f32 -> fp16)
    for (int i = tid; i < F_IN * F_HID / 4; i += 128) {
        int r = i >> 4, c4 = i & 15;
        float4 v = ((const float4*)W)[i];
        __half* p = &wh[r * 72 + c4 * 4];
        p[0] = __float2half(v.x); p[1] = __float2half(v.y);
        p[2] = __float2half(v.z); p[3] = __float2half(v.w);
    }
    // load x rows (scaled by norm_out, f32 -> fp16)
    for (int i = tid; i < 64 * 32; i += 128) {
        int r = i >> 5, kq = i & 31;
        int row = row0 + r;
        float4 v = make_float4(0.f, 0.f, 0.f, 0.f);
        float s = 0.f;
        if (row < N_NODES) {
            v = ((const float4*)x)[row * 32 + kq];
            s = g_norm_out[row];
        }
        __half* p = &xh[r * 136 + kq * 4];
        p[0] = __float2half(v.x * s); p[1] = __float2half(v.y * s);
        p[2] = __float2half(v.z * s); p[3] = __float2half(v.w * s);
    }
    __syncthreads();

    wmma::fragment<wmma::accumulator, 16, 16, 16, float> c[4];
#pragma unroll
    for (int n = 0; n < 4; n++) wmma::fill_fragment(c[n], 0.f);
#pragma unroll
    for (int k = 0; k < 8; k++) {
        wmma::fragment<wmma::matrix_a, 16, 16, 16, __half, wmma::row_major> a;
        wmma::load_matrix_sync(a, &xh[wid * 16 * 136 + k * 16], 136);
#pragma unroll
        for (int n = 0; n < 4; n++) {
            wmma::fragment<wmma::matrix_b, 16, 16, 16, __half, wmma::row_major> b;
            wmma::load_matrix_sync(b, &wh[k * 16 * 72 + n * 16], 72);
            wmma::mma_sync(c[n], a, b, c[n]);
        }
    }
    __syncthreads();   // everyone done reading xh/wh
#pragma unroll
    for (int n = 0; n < 4; n++)
        wmma::store_matrix_sync(&cs[wid * 16 * 64 + n * 16], c[n], 64, wmma::mem_row_major);
    __syncthreads();
    // convert to fp16 and store
    for (int i = tid; i < 64 * 16; i += 128) {
        int r = i >> 4, c4 = i & 15;
        int row = row0 + r;
        if (row < N_NODES) {
            const float* p = &cs[r * 64 + c4 * 4];
            union { __half2 h[2]; uint2 u; } pk;
            pk.h[0] = __floats2half2_rn(p[0], p[1]);
            pk.h[1] = __floats2half2_rn(p[2], p[3]);
            *reinterpret_cast<uint2*>(&g_h[row * F_HID + c4 * 4]) = pk.u;
        }
    }
}

// ---------------- GEMM2 (wmma fp16): g_h = fp16(g_t @ W2)  (K=64) ----------------
__global__ void __launch_bounds__(128) gemm2_kernel(const float* __restrict__ W) {
    __shared__ __align__(16) char blob[64 * 72 * 2 * 2];   // 18432 B
    __half* xh = (__half*)blob;                  // [64][72]
    __half* wh = (__half*)(blob + 64 * 72 * 2);  // [64][72]
    float*  cs = (float*)blob;                   // [64][64] reused (16384 < 18432)
    int tid = threadIdx.x;
    int wid = tid >> 5;
    int row0 = blockIdx.x * 64;

    // load W2 (64x64 f32 -> fp16)
    for (int i = tid; i < F_HID * F_HID / 4; i += 128) {
        int r = i >> 4, c4 = i & 15;
        float4 v = ((const float4*)W)[i];
        __half* p = &wh[r * 72 + c4 * 4];
        p[0] = __float2half(v.x); p[1] = __float2half(v.y);
        p[2] = __float2half(v.z); p[3] = __float2half(v.w);
    }
    // load g_t rows (already fp16): 64 rows x 8 uint4
    for (int i = tid; i < 64 * 8; i += 128) {
        int r = i >> 3, q = i & 7;
        int row = row0 + r;
        uint4 v = make_uint4(0u, 0u, 0u, 0u);
        if (row < N_NODES) v = ((const uint4*)g_t)[row * 8 + q];
        *reinterpret_cast<uint4*>(&xh[r * 72 + q * 8]) = v;
    }
    __syncthreads();

    wmma::fragment<wmma::accumulator, 16, 16, 16, float> c[4];
#pragma unroll
    for (int n = 0; n < 4; n++) wmma::fill_fragment(c[n], 0.f);
#pragma unroll
    for (int k = 0; k < 4; k++) {
        wmma::fragment<wmma::matrix_a, 16, 16, 16, __half, wmma::row_major> a;
        wmma::load_matrix_sync(a, &xh[wid * 16 * 72 + k * 16], 72);
#pragma unroll
        for (int n = 0; n < 4; n++) {
            wmma::fragment<wmma::matrix_b, 16, 16, 16, __half, wmma::row_major> b;
            wmma::load_matrix_sync(b, &wh[k * 16 * 72 + n * 16], 72);
            wmma::mma_sync(c[n], a, b, c[n]);
        }
    }
    __syncthreads();
#pragma unroll
    for (int n = 0; n < 4; n++)
        wmma::store_matrix_sync(&cs[wid * 16 * 64 + n * 16], c[n], 64, wmma::mem_row_major);
    __syncthreads();
    for (int i = tid; i < 64 * 16; i += 128) {
        int r = i >> 4, c4 = i & 15;
        int row = row0 + r;
        if (row < N_NODES) {
            const float* p = &cs[r * 64 + c4 * 4];
            union { __half2 h[2]; uint2 u; } pk;
            pk.h[0] = __floats2half2_rn(p[0], p[1]);
            pk.h[1] = __floats2half2_rn(p[2], p[3]);
            *reinterpret_cast<uint2*>(&g_h[row * F_HID + c4 * 4]) = pk.u;
        }
    }
}

// ---------------- gather core: one warp/node, half2/lane, 4-edge unroll ----------------
__device__ __forceinline__ float2 gather_sum(int node, int lane) {
    int beg = g_off[node], end = g_off[node + 1];
    const __half2* h2 = (const __half2*)g_h;
    float ax = 0.f, ay = 0.f, bx = 0.f, by = 0.f;
    float cx = 0.f, cy = 0.f, dx = 0.f, dy = 0.f;
    int j = beg;
    for (; j + 3 < end; j += 4) {
        int s0 = __ldg(&g_csr_src[j]);
        int s1 = __ldg(&g_csr_src[j + 1]);
        int s2 = __ldg(&g_csr_src[j + 2]);
        int s3 = __ldg(&g_csr_src[j + 3]);
        float2 v0 = __half22float2(h2[s0 * 32 + lane]);
        float2 v1 = __half22float2(h2[s1 * 32 + lane]);
        float2 v2 = __half22float2(h2[s2 * 32 + lane]);
        float2 v3 = __half22float2(h2[s3 * 32 + lane]);
        ax += v0.x; ay += v0.y;
        bx += v1.x; by += v1.y;
        cx += v2.x; cy += v2.y;
        dx += v3.x; dy += v3.y;
    }
    for (; j < end; j++) {
        int s = __ldg(&g_csr_src[j]);
        float2 v = __half22float2(h2[s * 32 + lane]);
        ax += v.x; ay += v.y;
    }
    return make_float2(ax + bx + cx + dx, ay + by + cy + dy);
}

// ---------------- gather layer 1: g_t = fp16(relu(sum*norm_in + b1) * norm_out) ----------------
__global__ void __launch_bounds__(256) gather1_kernel(const float* __restrict__ b1) {
    int node = blockIdx.x * 8 + (threadIdx.x >> 5);
    int lane = threadIdx.x & 31;
    if (node >= N_NODES) return;
    float2 a = gather_sum(node, lane);
    float ni = g_norm_in[node], no = g_norm_out[node];
    float2 bb = ((const float2*)b1)[lane];
    float ox = fmaxf(a.x * ni + bb.x, 0.f) * no;
    float oy = fmaxf(a.y * ni + bb.y, 0.f) * no;
    ((__half2*)g_t)[node * 32 + lane] = __floats2half2_rn(ox, oy);
}

// ---------------- gather layer 2: out = sum*norm_in + b2 (fp32 out) ----------------
__global__ void __launch_bounds__(256) gather2_kernel(const float* __restrict__ b2,
                                                      float* __restrict__ out) {
    int node = blockIdx.x * 8 + (threadIdx.x >> 5);
    int lane = threadIdx.x & 31;
    if (node >= N_NODES) return;
    float2 a = gather_sum(node, lane);
    float ni = g_norm_in[node];
    float2 bb = ((const float2*)b2)[lane];
    float2 o;
    o.x = a.x * ni + bb.x;
    o.y = a.y * ni + bb.y;
    ((float2*)out)[node * 32 + lane] = o;
}

extern "C" void kernel_launch(void* const* d_in, const int* in_sizes, int n_in,
                              void* d_out, int out_size) {
    const float* x   = (const float*)d_in[0];
    const int*   src = (const int*)  d_in[1];
    const int*   dst = (const int*)  d_in[2];
    const float* W1  = (const float*)d_in[3];
    const float* b1  = (const float*)d_in[4];
    const float* W2  = (const float*)d_in[5];
    const float* b2  = (const float*)d_in[6];
    float* out = (float*)d_out;

    const int T = 256;
    const int edgeBlocks   = (N_EDGES + T - 1) / T;   // 3125
    const int gemmBlocks   = (N_NODES + 63) / 64;     // 782
    const int gatherBlocks = (N_NODES + 7) / 8;       // 6250

    // degrees, norms, CSR
    count_deg_kernel<<<edgeBlocks, T>>>(src, dst);
    scanA_kernel<<<SCAN_NB, SCAN_B>>>();
    scanC_kernel<<<SCAN_NB, SCAN_B>>>();
    fill_kernel<<<edgeBlocks, T>>>(src, dst);

    // layer 1
    gemm1_kernel<<<gemmBlocks, 128>>>(x, W1);
    gather1_kernel<<<gatherBlocks, T>>>(b1);

    // layer 2
    gemm2_kernel<<<gemmBlocks, 128>>>(W2);
    gather2_kernel<<<gatherBlocks, T>>>(b2, out);
}

// round 13
// speedup vs baseline: 1.4705x; 1.0597x over previous
#include <cuda_runtime.h>
#include <cuda_fp16.h>
#include <mma.h>

using namespace nvcuda;

#define N_NODES 50000
#define N_EDGES 800000
#define F_IN    128
#define F_HID   64
#define SCAN_B  1024
#define SCAN_NB ((N_NODES + SCAN_B - 1) / SCAN_B)   // 49

// ---------------- scratch (no allocations allowed) ----------------
__device__ int   g_deg_out_i[N_NODES];   // zeroed at load; re-zeroed by scanC each call
__device__ int   g_deg_in_i [N_NODES];
__device__ float g_norm_out[N_NODES];
__device__ float g_norm_in [N_NODES];
__device__ int   g_off    [N_NODES + 1];
__device__ int   g_bsum   [64];
__device__ int   g_bpre   [64];
__device__ int   g_ticket;               // reset by scanA's last block
__device__ int   g_rank   [N_EDGES];     // edge rank within its dst bucket
__device__ int   g_csr_src[N_EDGES];
__device__ __align__(16) __half g_h[N_NODES * F_HID]; // gemm output, fp16 (128B rows)
__device__ __align__(16) __half g_t[N_NODES * F_HID]; // post-layer1 acts (pre-scaled, fp16)

// ---------------- degree count + per-edge rank capture ----------------
__global__ void count_deg_kernel(const int* __restrict__ src, const int* __restrict__ dst) {
    int e = blockIdx.x * blockDim.x + threadIdx.x;
    if (e < N_EDGES) {
        atomicAdd(&g_deg_out_i[src[e]], 1);
        g_rank[e] = atomicAdd(&g_deg_in_i[dst[e]], 1);
    }
}

// ---------------- scan phase A ----------------
__global__ void __launch_bounds__(SCAN_B) scanA_kernel() {
    __shared__ int warp_sums[32];
    __shared__ int is_last;
    int tid = threadIdx.x;
    int lane = tid & 31, wid = tid >> 5;
    int i = blockIdx.x * SCAN_B + tid;
    int v = (i < N_NODES) ? g_deg_in_i[i] : 0;
    int x = v;
#pragma unroll
    for (int o = 1; o < 32; o <<= 1) {
        int y = __shfl_up_sync(0xffffffffu, x, o);
        if (lane >= o) x += y;
    }
    if (lane == 31) warp_sums[wid] = x;
    __syncthreads();
    if (wid == 0) {
        int s = warp_sums[lane];
#pragma unroll
        for (int o = 1; o < 32; o <<= 1) {
            int y = __shfl_up_sync(0xffffffffu, s, o);
            if (lane >= o) s += y;
        }
        warp_sums[lane] = s;
    }
    __syncthreads();
    int excl = (wid ? warp_sums[wid - 1] : 0) + x - v;
    if (i < N_NODES) g_off[i] = excl;
    if (tid == SCAN_B - 1) {
        g_bsum[blockIdx.x] = excl + v;
        __threadfence();
    }
    __syncthreads();
    if (tid == 0)
        is_last = (atomicAdd(&g_ticket, 1) == (int)gridDim.x - 1);
    __syncthreads();
    if (is_last && wid == 0) {
        __threadfence();
        int acc = 0;
        for (int b = 0; b < SCAN_NB; b += 32) {
            int t = b + lane;
            int bv = (t < SCAN_NB) ? g_bsum[t] : 0;
            int bx = bv;
#pragma unroll
            for (int o = 1; o < 32; o <<= 1) {
                int y = __shfl_up_sync(0xffffffffu, bx, o);
                if (lane >= o) bx += y;
            }
            if (t < SCAN_NB) g_bpre[t] = acc + bx - bv;
            acc += __shfl_sync(0xffffffffu, bx, 31);
        }
        if (lane == 0) g_ticket = 0;
    }
}

// ---------------- scan phase C: finalize offsets + norms; re-zero degrees ----------------
__global__ void __launch_bounds__(SCAN_B) scanC_kernel() {
    int i = blockIdx.x * SCAN_B + threadIdx.x;
    if (i < N_NODES) {
        int off = g_off[i] + g_bpre[blockIdx.x];
        g_off[i] = off;
        g_norm_out[i] = rsqrtf(fmaxf((float)g_deg_out_i[i], 1.f));
        g_norm_in [i] = rsqrtf(fmaxf((float)g_deg_in_i [i], 1.f));
        g_deg_out_i[i] = 0;
        g_deg_in_i [i] = 0;
    }
    if (i == 0) g_off[N_NODES] = N_EDGES;
}

// ---------------- CSR fill: atomic-free scalar (measured best) ----------------
__global__ void fill_kernel(const int* __restrict__ src, const int* __restrict__ dst) {
    int e = blockIdx.x * blockDim.x + threadIdx.x;
    if (e < N_EDGES) {
        int pos = __ldg(&g_off[dst[e]]) + g_rank[e];
        g_csr_src[pos] = src[e];
    }
}

// ---------------- GEMM1 (wmma fp16): g_h = fp16((x * norm_out) @ W1) ----------------
__global__ void __launch_bounds__(128) gemm1_kernel(const float* __restrict__ x,
                                                    const float* __restrict__ W) {
    __shared__ __align__(16) char blob[64 * 136 * 2 + 128 * 72 * 2];  // 35840 B
    __half* xh = (__half*)blob;                    // [64][136]
    __half* wh = (__half*)(blob + 64 * 136 * 2);   // [128][72]
    float*  cs = (float*)blob;                     // [64][64], reused after compute
    int tid = threadIdx.x;
    int wid = tid >> 5;
    int row0 = blockIdx.x * 64;

    for (int i = tid; i < F_IN * F_HID / 4; i += 128) {
        int r = i >> 4, c4 = i & 15;
        float4 v = ((const float4*)W)[i];
        __half* p = &wh[r * 72 + c4 * 4];
        p[0] = __float2half(v.x); p[1] = __float2half(v.y);
        p[2] = __float2half(v.z); p[3] = __float2half(v.w);
    }
    for (int i = tid; i < 64 * 32; i += 128) {
        int r = i >> 5, kq = i & 31;
        int row = row0 + r;
        float4 v = make_float4(0.f, 0.f, 0.f, 0.f);
        float s = 0.f;
        if (row < N_NODES) {
            v = ((const float4*)x)[row * 32 + kq];
            s = g_norm_out[row];
        }
        __half* p = &xh[r * 136 + kq * 4];
        p[0] = __float2half(v.x * s); p[1] = __float2half(v.y * s);
        p[2] = __float2half(v.z * s); p[3] = __float2half(v.w * s);
    }
    __syncthreads();

    wmma::fragment<wmma::accumulator, 16, 16, 16, float> c[4];
#pragma unroll
    for (int n = 0; n < 4; n++) wmma::fill_fragment(c[n], 0.f);
#pragma unroll
    for (int k = 0; k < 8; k++) {
        wmma::fragment<wmma::matrix_a, 16, 16, 16, __half, wmma::row_major> a;
        wmma::load_matrix_sync(a, &xh[wid * 16 * 136 + k * 16], 136);
#pragma unroll
        for (int n = 0; n < 4; n++) {
            wmma::fragment<wmma::matrix_b, 16, 16, 16, __half, wmma::row_major> b;
            wmma::load_matrix_sync(b, &wh[k * 16 * 72 + n * 16], 72);
            wmma::mma_sync(c[n], a, b, c[n]);
        }
    }
    __syncthreads();
#pragma unroll
    for (int n = 0; n < 4; n++)
        wmma::store_matrix_sync(&cs[wid * 16 * 64 + n * 16], c[n], 64, wmma::mem_row_major);
    __syncthreads();
    for (int i = tid; i < 64 * 16; i += 128) {
        int r = i >> 4, c4 = i & 15;
        int row = row0 + r;
        if (row < N_NODES) {
            const float* p = &cs[r * 64 + c4 * 4];
            union { __half2 h[2]; uint2 u; } pk;
            pk.h[0] = __floats2half2_rn(p[0], p[1]);
            pk.h[1] = __floats2half2_rn(p[2], p[3]);
            *reinterpret_cast<uint2*>(&g_h[row * F_HID + c4 * 4]) = pk.u;
        }
    }
}

// ---------------- GEMM2 (wmma fp16): g_h = fp16(g_t @ W2)  (K=64) ----------------
__global__ void __launch_bounds__(128) gemm2_kernel(const float* __restrict__ W) {
    __shared__ __align__(16) char blob[64 * 72 * 2 * 2];   // 18432 B
    __half* xh = (__half*)blob;                  // [64][72]
    __half* wh = (__half*)(blob + 64 * 72 * 2);  // [64][72]
    float*  cs = (float*)blob;                   // [64][64] reused
    int tid = threadIdx.x;
    int wid = tid >> 5;
    int row0 = blockIdx.x * 64;

    for (int i = tid; i < F_HID * F_HID / 4; i += 128) {
        int r = i >> 4, c4 = i & 15;
        float4 v = ((const float4*)W)[i];
        __half* p = &wh[r * 72 + c4 * 4];
        p[0] = __float2half(v.x); p[1] = __float2half(v.y);
        p[2] = __float2half(v.z); p[3] = __float2half(v.w);
    }
    for (int i = tid; i < 64 * 8; i += 128) {
        int r = i >> 3, q = i & 7;
        int row = row0 + r;
        uint4 v = make_uint4(0u, 0u, 0u, 0u);
        if (row < N_NODES) v = ((const uint4*)g_t)[row * 8 + q];
        *reinterpret_cast<uint4*>(&xh[r * 72 + q * 8]) = v;
    }
    __syncthreads();

    wmma::fragment<wmma::accumulator, 16, 16, 16, float> c[4];
#pragma unroll
    for (int n = 0; n < 4; n++) wmma::fill_fragment(c[n], 0.f);
#pragma unroll
    for (int k = 0; k < 4; k++) {
        wmma::fragment<wmma::matrix_a, 16, 16, 16, __half, wmma::row_major> a;
        wmma::load_matrix_sync(a, &xh[wid * 16 * 72 + k * 16], 72);
#pragma unroll
        for (int n = 0; n < 4; n++) {
            wmma::fragment<wmma::matrix_b, 16, 16, 16, __half, wmma::row_major> b;
            wmma::load_matrix_sync(b, &wh[k * 16 * 72 + n * 16], 72);
            wmma::mma_sync(c[n], a, b, c[n]);
        }
    }
    __syncthreads();
#pragma unroll
    for (int n = 0; n < 4; n++)
        wmma::store_matrix_sync(&cs[wid * 16 * 64 + n * 16], c[n], 64, wmma::mem_row_major);
    __syncthreads();
    for (int i = tid; i < 64 * 16; i += 128) {
        int r = i >> 4, c4 = i & 15;
        int row = row0 + r;
        if (row < N_NODES) {
            const float* p = &cs[r * 64 + c4 * 4];
            union { __half2 h[2]; uint2 u; } pk;
            pk.h[0] = __floats2half2_rn(p[0], p[1]);
            pk.h[1] = __floats2half2_rn(p[2], p[3]);
            *reinterpret_cast<uint2*>(&g_h[row * F_HID + c4 * 4]) = pk.u;
        }
    }
}

// ---------------- gather core: 2 nodes/warp, 16 lanes/node, half4/lane, 4-edge unroll ----
// returns per-lane float4 = 4 features [sub*4, sub*4+4) of this half-warp's node.
__device__ __forceinline__ float4 gather_sum16(int node, int sub) {
    int beg = g_off[node];
    int deg = g_off[node + 1] - beg;
    int dmax = max(deg, __shfl_xor_sync(0xffffffffu, deg, 16));
    const uint2* h4 = (const uint2*)g_h;     // 8 B = 4 halves; row = 16 uint2
    float4 a0 = make_float4(0.f, 0.f, 0.f, 0.f);
    float4 a1 = a0, a2 = a0, a3 = a0;
    for (int j = 0; j < dmax; j += 4) {
        int s0 = (j + 0 < deg) ? __ldg(&g_csr_src[beg + j + 0]) : -1;
        int s1 = (j + 1 < deg) ? __ldg(&g_csr_src[beg + j + 1]) : -1;
        int s2 = (j + 2 < deg) ? __ldg(&g_csr_src[beg + j + 2]) : -1;
        int s3 = (j + 3 < deg) ? __ldg(&g_csr_src[beg + j + 3]) : -1;
        if (s0 >= 0) {
            uint2 r = h4[s0 * 16 + sub];
            float2 p = __half22float2(*(__half2*)&r.x);
            float2 q = __half22float2(*(__half2*)&r.y);
            a0.x += p.x; a0.y += p.y; a0.z += q.x; a0.w += q.y;
        }
        if (s1 >= 0) {
            uint2 r = h4[s1 * 16 + sub];
            float2 p = __half22float2(*(__half2*)&r.x);
            float2 q = __half22float2(*(__half2*)&r.y);
            a1.x += p.x; a1.y += p.y; a1.z += q.x; a1.w += q.y;
        }
        if (s2 >= 0) {
            uint2 r = h4[s2 * 16 + sub];
            float2 p = __half22float2(*(__half2*)&r.x);
            float2 q = __half22float2(*(__half2*)&r.y);
            a2.x += p.x; a2.y += p.y; a2.z += q.x; a2.w += q.y;
        }
        if (s3 >= 0) {
            uint2 r = h4[s3 * 16 + sub];
            float2 p = __half22float2(*(__half2*)&r.x);
            float2 q = __half22float2(*(__half2*)&r.y);
            a3.x += p.x; a3.y += p.y; a3.z += q.x; a3.w += q.y;
        }
    }
    a0.x += a1.x + a2.x + a3.x;
    a0.y += a1.y + a2.y + a3.y;
    a0.z += a1.z + a2.z + a3.z;
    a0.w += a1.w + a2.w + a3.w;
    return a0;
}

// ---------------- gather layer 1: g_t = fp16(relu(sum*norm_in + b1) * norm_out) ----------
// 256 threads = 16 half-warps = 16 nodes/block; 50000/16 = 3125 blocks exact.
__global__ void __launch_bounds__(256) gather1_kernel(const float* __restrict__ b1) {
    int node = blockIdx.x * 16 + (threadIdx.x >> 4);
    int sub = threadIdx.x & 15;
    float4 a = gather_sum16(node, sub);
    float ni = g_norm_in[node], no = g_norm_out[node];
    float4 bb = ((const float4*)b1)[sub];
    float ox = fmaxf(a.x * ni + bb.x, 0.f) * no;
    float oy = fmaxf(a.y * ni + bb.y, 0.f) * no;
    float oz = fmaxf(a.z * ni + bb.z, 0.f) * no;
    float ow = fmaxf(a.w * ni + bb.w, 0.f) * no;
    union { __half2 h[2]; uint2 u; } pk;
    pk.h[0] = __floats2half2_rn(ox, oy);
    pk.h[1] = __floats2half2_rn(oz, ow);
    ((uint2*)g_t)[node * 16 + sub] = pk.u;
}

// ---------------- gather layer 2: out = sum*norm_in + b2 (fp32 out) ----------------
__global__ void __launch_bounds__(256) gather2_kernel(const float* __restrict__ b2,
                                                      float* __restrict__ out) {
    int node = blockIdx.x * 16 + (threadIdx.x >> 4);
    int sub = threadIdx.x & 15;
    float4 a = gather_sum16(node, sub);
    float ni = g_norm_in[node];
    float4 bb = ((const float4*)b2)[sub];
    float4 o;
    o.x = a.x * ni + bb.x;
    o.y = a.y * ni + bb.y;
    o.z = a.z * ni + bb.z;
    o.w = a.w * ni + bb.w;
    ((float4*)out)[node * 16 + sub] = o;
}

extern "C" void kernel_launch(void* const* d_in, const int* in_sizes, int n_in,
                              void* d_out, int out_size) {
    const float* x   = (const float*)d_in[0];
    const int*   src = (const int*)  d_in[1];
    const int*   dst = (const int*)  d_in[2];
    const float* W1  = (const float*)d_in[3];
    const float* b1  = (const float*)d_in[4];
    const float* W2  = (const float*)d_in[5];
    const float* b2  = (const float*)d_in[6];
    float* out = (float*)d_out;

    const int T = 256;
    const int edgeBlocks   = (N_EDGES + T - 1) / T;   // 3125
    const int gemmBlocks   = (N_NODES + 63) / 64;     // 782
    const int gatherBlocks = N_NODES / 16;            // 3125 exact

    // degrees, norms, CSR
    count_deg_kernel<<<edgeBlocks, T>>>(src, dst);
    scanA_kernel<<<SCAN_NB, SCAN_B>>>();
    scanC_kernel<<<SCAN_NB, SCAN_B>>>();
    fill_kernel<<<edgeBlocks, T>>>(src, dst);

    // layer 1
    gemm1_kernel<<<gemmBlocks, 128>>>(x, W1);
    gather1_kernel<<<gatherBlocks, T>>>(b1);

    // layer 2
    gemm2_kernel<<<gemmBlocks, 128>>>(W2);
    gather2_kernel<<<gatherBlocks, T>>>(b2, out);
}